// round 12
// baseline (speedup 1.0000x reference)
#include <cuda_runtime.h>
#include <math.h>

#define IDIM 128
#define HDIM 1024
#define NITER 4
#define NTOK 2048
#define NBLK 148            // one block per SM, balanced wave
#define NTHREADS 512        // 16 warps
#define TOKMAX 14           // blocks 0..123: 14 tokens, 124..147: 13
#define XPAD 384            // padded x_res (data at [127,254], zeros elsewhere)
#define WST_STRIDE 33       // float4 stride per staged weight row (conflict-free)
#define HROW 264            // h row stride in floats

typedef unsigned long long ull;

__device__ float g_psum[NBLK];
__device__ float g_pcnt[NBLK];
__device__ int   g_cnt = 0;          // last-block ticket; reset by last block

// ---- packed fp32x2 helpers ----
__device__ __forceinline__ ull pk(float lo, float hi) {
    ull r; asm("mov.b64 %0, {%1, %2};" : "=l"(r) : "f"(lo), "f"(hi)); return r;
}
__device__ __forceinline__ void fma2(ull& acc, ull a, ull b) {
    asm("fma.rn.f32x2 %0, %1, %2, %3;" : "=l"(acc) : "l"(a), "l"(b), "l"(acc));
}
__device__ __forceinline__ float2 upk(ull v) {
    float2 r; asm("mov.b64 {%0, %1}, %2;" : "=f"(r.x), "=f"(r.y) : "l"(v)); return r;
}
__device__ __forceinline__ void lds2(ull& a, ull& b, unsigned addr) {
    asm("ld.shared.v2.b64 {%0, %1}, [%2];" : "=l"(a), "=l"(b) : "r"(addr));
}
__device__ __forceinline__ unsigned s2u(const void* p) {
    unsigned a;
    asm("{ .reg .u64 t; cvta.to.shared.u64 t, %1; cvt.u32.u64 %0, t; }"
        : "=r"(a) : "l"(p));
    return a;
}
// async 16B global->shared copy (LDGSTS), bypasses register file
__device__ __forceinline__ void cpa16(unsigned saddr, const void* g) {
    asm volatile("cp.async.cg.shared.global [%0], [%1], 16;"
                 :: "r"(saddr), "l"(g) : "memory");
}
__device__ __forceinline__ void cpa_commit() {
    asm volatile("cp.async.commit_group;" ::: "memory");
}
__device__ __forceinline__ void cpa_wait0() {
    asm volatile("cp.async.wait_group 0;" ::: "memory");
}

struct __align__(16) Smem {
    float4 wstA[IDIM * WST_STRIDE];    // 67584 B  staged weights, buffer A
    float4 wstB[IDIM * WST_STRIDE];    // 67584 B  staged weights, buffer B
    float  xp[TOKMAX][XPAD];           // 21504 B  padded x_res
    float  xa[TOKMAX][IDIM];           // 7168 B
    float  h[TOKMAX][HROW];            // 14784 B
    float  yres[TOKMAX][IDIM];         // 7168 B
    float  red[16];
    float  red2[16];
    float  fred[256];
    float  fred2[256];
    int    islast;
    unsigned char ymask[TOKMAX][IDIM]; // 1792 B
};

extern __shared__ unsigned char smem_raw[];

__global__ void __launch_bounds__(NTHREADS, 1)
net_main_kernel(const float* __restrict__ x, const float* __restrict__ y,
                const float* __restrict__ w1, const float* __restrict__ b1,
                const float* __restrict__ w2, const float* __restrict__ b2,
                float* __restrict__ out)
{
    Smem& sm = *reinterpret_cast<Smem*>(smem_raw);
    const int tid  = threadIdx.x;
    const int lane = tid & 31;
    const int wid  = tid >> 5;
    const int blk  = blockIdx.x;
    const int tcnt = (blk < 124) ? 14 : 13;
    const int tok0 = (blk < 124) ? blk * 14 : 124 * 14 + (blk - 124) * 13;

    // ---- zero padded x buffer ----
    for (int e = tid; e < TOKMAX * XPAD; e += NTHREADS)
        (&sm.xp[0][0])[e] = 0.f;
    __syncthreads();

    // ---- load x, y, mask; count unmasked ----
    float cnt = 0.f;
    for (int e = tid; e < tcnt * IDIM; e += NTHREADS) {
        int m = e >> 7, d = e & 127;
        sm.xp[m][127 + d] = x[(tok0 + m) * IDIM + d];
        float yv = y[(tok0 + m) * IDIM + d];
        sm.yres[m][d] = yv;
        unsigned char msk = (yv == 10000.0f) ? 1 : 0;
        sm.ymask[m][d] = msk;
        cnt += msk ? 0.f : 1.f;
    }

    float sqacc = 0.f;
    const int o = tid & 127;
    const int g = tid >> 7;

    int  slot[4];
    bool sv[4];
    #pragma unroll
    for (int t = 0; t < 4; ++t) { slot[t] = g + 4 * t; sv[t] = slot[t] < tcnt; }

    const unsigned wrowA = s2u(&sm.wstA[o * WST_STRIDE]);
    const unsigned wrowB = s2u(&sm.wstB[o * WST_STRIDE]);
    unsigned xa_a[4], h_a[4];
    #pragma unroll
    for (int t = 0; t < 4; ++t) {
        int s = sv[t] ? slot[t] : 0;
        xa_a[t] = s2u(&sm.xa[s][0]);
        h_a[t]  = s2u(&sm.h[s][0]);
    }

    const float4* wg2 = reinterpret_cast<const float4*>(w2);
    // staging addresses: thread covers j = tid + r*512 -> row = (tid>>5)+r*16, col = tid&31
    const int jrow = tid >> 5;
    const int jcol = tid & 31;
    unsigned stA[8], stB[8];
    #pragma unroll
    for (int r = 0; r < 8; ++r) {
        stA[r] = s2u(&sm.wstA[(jrow + r * 16) * WST_STRIDE + jcol]);
        stB[r] = s2u(&sm.wstB[(jrow + r * 16) * WST_STRIDE + jcol]);
    }

    for (int it = 0; it < NITER; ++it) {
        __syncthreads();   // S0: yres/xp stable; all prior wst reads done

        // async-stage w1 chunk0 -> bufA (in flight during phase A)
        {
            const float4* wg = reinterpret_cast<const float4*>(
                w1 + (size_t)(it * 256) * IDIM);
            #pragma unroll
            for (int r = 0; r < 8; ++r) cpa16(stA[r], wg + tid + r * 512);
            cpa_commit();
        }

        // ================= Phase A: per-warp token pipeline (FFMA2) =========
        if (wid < tcnt) {
            const int m = wid;
            float* xpm = sm.xp[m];
            const float* ym = sm.yres[m];
            const unsigned aA = s2u(xpm);
            const unsigned aY = s2u(ym);

            float ny2 = 0.f;
            #pragma unroll
            for (int j = 0; j < 4; ++j) { float vv = ym[lane + 32 * j]; ny2 += vv * vv; }
            #pragma unroll
            for (int off = 16; off; off >>= 1) ny2 += __shfl_xor_sync(~0u, ny2, off);
            float ny = sqrtf(ny2);

            ull num2[8], dn2[8];
            #pragma unroll
            for (int k = 0; k < 8; ++k) { num2[k] = 0ull; dn2[k] = 0ull; }
            #pragma unroll
            for (int b = 0; b < 2; ++b) {
                const int q0 = lane + 32 * b;
                const int k0 = 4 * b;
                ull Alo, Ahi;
                lds2(Alo, Ahi, aA + q0 * 16);
                #pragma unroll 8
                for (int d4 = 0; d4 < 32; ++d4) {
                    ull ylo, yhi, AnL, AnH;
                    lds2(ylo, yhi, aY + d4 * 16);
                    lds2(AnL, AnH, aA + (q0 + d4 + 1) * 16);
                    float2 fa0 = upk(Alo);   // x0,x1
                    float2 fa1 = upk(Ahi);   // x2,x3
                    float2 fa2 = upk(AnL);   // x4,x5
                    float2 fa3 = upk(AnH);   // x6,x7
                    ull p12 = pk(fa0.y, fa1.x);
                    ull p34 = pk(fa1.y, fa2.x);
                    ull p56 = pk(fa2.y, fa3.x);
                    // j=0: (x0,x1),(x2,x3)
                    fma2(num2[k0+0], ylo, Alo); fma2(num2[k0+0], yhi, Ahi);
                    fma2(dn2[k0+0],  Alo, Alo); fma2(dn2[k0+0],  Ahi, Ahi);
                    // j=1: (x1,x2),(x3,x4)
                    fma2(num2[k0+1], ylo, p12); fma2(num2[k0+1], yhi, p34);
                    fma2(dn2[k0+1],  p12, p12); fma2(dn2[k0+1],  p34, p34);
                    // j=2: (x2,x3),(x4,x5)
                    fma2(num2[k0+2], ylo, Ahi); fma2(num2[k0+2], yhi, AnL);
                    fma2(dn2[k0+2],  Ahi, Ahi); fma2(dn2[k0+2],  AnL, AnL);
                    // j=3: (x3,x4),(x5,x6)
                    fma2(num2[k0+3], ylo, p34); fma2(num2[k0+3], yhi, p56);
                    fma2(dn2[k0+3],  p34, p34); fma2(dn2[k0+3],  p56, p56);
                    Alo = AnL; Ahi = AnH;
                }
            }

            float best = -INFINITY; int bs = 0x7fffffff;
            #pragma unroll
            for (int b = 0; b < 2; ++b)
            #pragma unroll
            for (int j = 0; j < 4; ++j) {
                int s = 4 * lane + 128 * b + j;
                if (s < 255) {
                    int kk = 4 * b + j;
                    float2 nn = upk(num2[kk]);
                    float2 qq = upk(dn2[kk]);
                    float numv = nn.x + nn.y;
                    float dnv  = qq.x + qq.y;
                    float den = ny * sqrtf(dnv);
                    float sim = (den == 0.f) ? 0.f : numv / den;
                    if (sim > best) { best = sim; bs = s; }
                }
            }
            #pragma unroll
            for (int off = 16; off; off >>= 1) {
                float ob = __shfl_xor_sync(~0u, best, off);
                int   os = __shfl_xor_sync(~0u, bs,   off);
                if (ob > best || (ob == best && os < bs)) { best = ob; bs = os; }
            }
            const int idx = bs;

            float xav[4], z[4];
            float zmax = -INFINITY;
            #pragma unroll
            for (int j = 0; j < 4; ++j) {
                int d = lane + 32 * j;
                xav[j] = xpm[idx + d];
                z[j]   = xav[j] * ym[d];
                zmax   = fmaxf(zmax, z[j]);
            }
            #pragma unroll
            for (int off = 16; off; off >>= 1) zmax = fmaxf(zmax, __shfl_xor_sync(~0u, zmax, off));
            float es = 0.f, e[4];
            #pragma unroll
            for (int j = 0; j < 4; ++j) { e[j] = expf(z[j] - zmax); es += e[j]; }
            #pragma unroll
            for (int off = 16; off; off >>= 1) es += __shfl_xor_sync(~0u, es, off);
            #pragma unroll
            for (int j = 0; j < 4; ++j) {
                int d = lane + 32 * j;
                sm.xa[m][d] = xav[j] * (e[j] / es);
            }
            __syncwarp();
            #pragma unroll
            for (int j = 0; j < 4; ++j) {
                int d = lane + 32 * j;
                int src = d + 127 - idx;
                float xe = (src >= 0 && src < 128) ? sm.xa[m][src] : 0.f;
                xpm[127 + d] -= xe;
            }
        }

        cpa_wait0();
        __syncthreads();   // S1: xa + bufA ready

        // ================= Phase B =================
        ull accB[4];
        float b2v = b2[o];
        ull accc[4];
        accc[0] = pk(b2v, 0.f); accc[1] = pk(b2v, 0.f);
        accc[2] = pk(b2v, 0.f); accc[3] = pk(b2v, 0.f);

        // ---- B chunk0: stage w1c1 -> bufB (async); compute from bufA ----
        {
            const float4* wg = reinterpret_cast<const float4*>(
                w1 + (size_t)(it * 256 + 128) * IDIM);
            #pragma unroll
            for (int r = 0; r < 8; ++r) cpa16(stB[r], wg + tid + r * 512);
            cpa_commit();

            float bv = b1[it * 256 + o];
            accB[0] = pk(bv, 0.f); accB[1] = pk(bv, 0.f);
            accB[2] = pk(bv, 0.f); accB[3] = pk(bv, 0.f);
            #pragma unroll 8
            for (int d4 = 0; d4 < 32; ++d4) {
                ull w01, w23;
                lds2(w01, w23, wrowA + d4 * 16);
                #pragma unroll
                for (int t = 0; t < 4; ++t) {
                    ull x01, x23;
                    lds2(x01, x23, xa_a[t] + d4 * 16);
                    fma2(accB[t], w01, x01);
                    fma2(accB[t], w23, x23);
                }
            }
            #pragma unroll
            for (int t = 0; t < 4; ++t) {
                if (sv[t]) {
                    float2 a = upk(accB[t]);
                    sm.h[slot[t]][o] = a.x + a.y;
                }
            }
        }
        cpa_wait0();
        __syncthreads();   // SB1

        // ---- B chunk1: stage w2c0 -> bufA (async); compute from bufB ----
        {
            #pragma unroll
            for (int r = 0; r < 8; ++r) {
                int j = tid + r * 512;
                cpa16(stA[r], wg2 + (size_t)(j >> 5) * (HDIM / 4) + it * 64 + (j & 31));
            }
            cpa_commit();

            float bv = b1[it * 256 + 128 + o];
            accB[0] = pk(bv, 0.f); accB[1] = pk(bv, 0.f);
            accB[2] = pk(bv, 0.f); accB[3] = pk(bv, 0.f);
            #pragma unroll 8
            for (int d4 = 0; d4 < 32; ++d4) {
                ull w01, w23;
                lds2(w01, w23, wrowB + d4 * 16);
                #pragma unroll
                for (int t = 0; t < 4; ++t) {
                    ull x01, x23;
                    lds2(x01, x23, xa_a[t] + d4 * 16);
                    fma2(accB[t], w01, x01);
                    fma2(accB[t], w23, x23);
                }
            }
            #pragma unroll
            for (int t = 0; t < 4; ++t) {
                if (sv[t]) {
                    float2 a = upk(accB[t]);
                    sm.h[slot[t]][128 + o] = a.x + a.y;
                }
            }
        }
        cpa_wait0();
        __syncthreads();   // SB2

        // ---- C chunk0: stage w2c1 -> bufB (async); compute from bufA ----
        {
            #pragma unroll
            for (int r = 0; r < 8; ++r) {
                int j = tid + r * 512;
                cpa16(stB[r], wg2 + (size_t)(j >> 5) * (HDIM / 4) + it * 64 + 32 + (j & 31));
            }
            cpa_commit();

            #pragma unroll 8
            for (int c4 = 0; c4 < 32; ++c4) {
                ull w01, w23;
                lds2(w01, w23, wrowA + c4 * 16);
                #pragma unroll
                for (int t = 0; t < 4; ++t) {
                    ull h01, h23;
                    lds2(h01, h23, h_a[t] + c4 * 16);
                    fma2(accc[t], w01, h01);
                    fma2(accc[t], w23, h23);
                }
            }
        }
        cpa_wait0();
        __syncthreads();   // SB3

        // ---- C chunk1: compute from bufB ----
        #pragma unroll 8
        for (int c4 = 0; c4 < 32; ++c4) {
            ull w01, w23;
            lds2(w01, w23, wrowB + c4 * 16);
            #pragma unroll
            for (int t = 0; t < 4; ++t) {
                ull h01, h23;
                lds2(h01, h23, h_a[t] + 512 + c4 * 16);
                fma2(accc[t], w01, h01);
                fma2(accc[t], w23, h23);
            }
        }

        // ---- masked squared error + y_res update ----
        #pragma unroll
        for (int t = 0; t < 4; ++t) {
            if (sv[t]) {
                int m = slot[t];
                float2 c2 = upk(accc[t]);
                float ye = c2.x + c2.y;
                float yr = sm.yres[m][o];
                if (!sm.ymask[m][o]) { float dd = ye - yr; sqacc += dd * dd; }
                sm.yres[m][o] = yr - ye;
            }
        }
        // loop-top S0 orders these writes before next phase A / bufA restage
    }

    // ---- block reduction ----
    #pragma unroll
    for (int off = 16; off; off >>= 1) {
        sqacc += __shfl_xor_sync(~0u, sqacc, off);
        cnt   += __shfl_xor_sync(~0u, cnt,   off);
    }
    if (lane == 0) { sm.red[wid] = sqacc; sm.red2[wid] = cnt; }
    __syncthreads();
    if (tid == 0) {
        float s = 0.f, c = 0.f;
        #pragma unroll
        for (int w = 0; w < 16; ++w) { s += sm.red[w]; c += sm.red2[w]; }
        g_psum[blk] = s;
        g_pcnt[blk] = c;
        __threadfence();
        int ticket = atomicAdd(&g_cnt, 1);
        __threadfence();
        sm.islast = (ticket == NBLK - 1) ? 1 : 0;
    }
    __syncthreads();

    // ---- last block: deterministic global reduction ----
    if (sm.islast) {
        int t = tid;
        if (t < 256) {
            sm.fred[t]  = (t < NBLK) ? g_psum[t] : 0.f;
            sm.fred2[t] = (t < NBLK) ? g_pcnt[t] : 0.f;
        }
        __syncthreads();
        for (int off = 128; off; off >>= 1) {
            if (t < off) { sm.fred[t] += sm.fred[t + off]; sm.fred2[t] += sm.fred2[t + off]; }
            __syncthreads();
        }
        if (t == 0) {
            out[0] = sm.fred[0] / (4.0f * sm.fred2[0]);
            g_cnt = 0;   // reset for next graph replay
        }
    }
}

extern "C" void kernel_launch(void* const* d_in, const int* in_sizes, int n_in,
                              void* d_out, int out_size)
{
    (void)in_sizes; (void)n_in; (void)out_size;
    const float* x  = (const float*)d_in[0];
    const float* y  = (const float*)d_in[1];
    const float* w1 = (const float*)d_in[2];
    const float* b1 = (const float*)d_in[3];
    const float* w2 = (const float*)d_in[4];
    const float* b2 = (const float*)d_in[5];
    float* out = (float*)d_out;

    cudaFuncSetAttribute(net_main_kernel,
                         cudaFuncAttributeMaxDynamicSharedMemorySize,
                         (int)sizeof(Smem));
    net_main_kernel<<<NBLK, NTHREADS, sizeof(Smem)>>>(x, y, w1, b1, w2, b2, out);
}

// round 13
// speedup vs baseline: 1.8959x; 1.8959x over previous
#include <cuda_runtime.h>
#include <math.h>

#define IDIM 128
#define HDIM 1024
#define NITER 4
#define NTOK 2048
#define NBLK 148            // one block per SM, balanced wave
#define NTHREADS 512        // 16 warps
#define TOKMAX 14           // blocks 0..123: 14 tokens, 124..147: 13
#define XPAD 384            // padded x_res (data at [127,254], zeros elsewhere)
#define WST_STRIDE 33       // float4 stride per staged weight row (conflict-free)
#define HROW 264            // h row stride in floats

typedef unsigned long long ull;

__device__ float g_psum[NBLK];
__device__ float g_pcnt[NBLK];
__device__ int   g_cnt = 0;          // last-block ticket; reset by last block

// ---- packed fp32x2 helpers ----
__device__ __forceinline__ ull pk(float lo, float hi) {
    ull r; asm("mov.b64 %0, {%1, %2};" : "=l"(r) : "f"(lo), "f"(hi)); return r;
}
__device__ __forceinline__ void fma2(ull& acc, ull a, ull b) {
    asm("fma.rn.f32x2 %0, %1, %2, %3;" : "=l"(acc) : "l"(a), "l"(b), "l"(acc));
}
__device__ __forceinline__ float2 upk(ull v) {
    float2 r; asm("mov.b64 {%0, %1}, %2;" : "=f"(r.x), "=f"(r.y) : "l"(v)); return r;
}
__device__ __forceinline__ void lds2(ull& a, ull& b, unsigned addr) {
    asm("ld.shared.v2.b64 {%0, %1}, [%2];" : "=l"(a), "=l"(b) : "r"(addr));
}
__device__ __forceinline__ unsigned s2u(const void* p) {
    unsigned a;
    asm("{ .reg .u64 t; cvta.to.shared.u64 t, %1; cvt.u32.u64 %0, t; }"
        : "=r"(a) : "l"(p));
    return a;
}
__device__ __forceinline__ void cpa16(unsigned saddr, const void* g) {
    asm volatile("cp.async.cg.shared.global [%0], [%1], 16;"
                 :: "r"(saddr), "l"(g) : "memory");
}
__device__ __forceinline__ void cpa_commit() {
    asm volatile("cp.async.commit_group;" ::: "memory");
}
__device__ __forceinline__ void cpa_wait0() {
    asm volatile("cp.async.wait_group 0;" ::: "memory");
}

struct __align__(16) Smem {
    float4 wstA[IDIM * WST_STRIDE];    // 67584 B  staged weights, buffer A
    float4 wstB[IDIM * WST_STRIDE];    // 67584 B  staged weights, buffer B
    float  xp[TOKMAX][XPAD];           // 21504 B  padded x_res
    float  xps[TOKMAX][XPAD];          // 21504 B  shadow: xps[i] = xp[i+1]
    float  xa[TOKMAX][IDIM];           // 7168 B
    float  h[TOKMAX][HROW];            // 14784 B
    float  yres[TOKMAX][IDIM];         // 7168 B
    float  red[16];
    float  red2[16];
    float  fred[256];
    float  fred2[256];
    int    islast;
    unsigned char ymask[TOKMAX][IDIM]; // 1792 B
};

extern __shared__ unsigned char smem_raw[];

__global__ void __launch_bounds__(NTHREADS, 1)
net_main_kernel(const float* __restrict__ x, const float* __restrict__ y,
                const float* __restrict__ w1, const float* __restrict__ b1,
                const float* __restrict__ w2, const float* __restrict__ b2,
                float* __restrict__ out)
{
    Smem& sm = *reinterpret_cast<Smem*>(smem_raw);
    const int tid  = threadIdx.x;
    const int lane = tid & 31;
    const int wid  = tid >> 5;
    const int blk  = blockIdx.x;
    const int tcnt = (blk < 124) ? 14 : 13;
    const int tok0 = (blk < 124) ? blk * 14 : 124 * 14 + (blk - 124) * 13;

    // ---- zero padded x buffers ----
    for (int e = tid; e < TOKMAX * XPAD; e += NTHREADS) {
        (&sm.xp[0][0])[e]  = 0.f;
        (&sm.xps[0][0])[e] = 0.f;
    }
    __syncthreads();

    // ---- load x (both copies), y, mask; count unmasked ----
    float cnt = 0.f;
    for (int e = tid; e < tcnt * IDIM; e += NTHREADS) {
        int m = e >> 7, d = e & 127;
        float xv = x[(tok0 + m) * IDIM + d];
        sm.xp[m][127 + d]  = xv;
        sm.xps[m][126 + d] = xv;
        float yv = y[(tok0 + m) * IDIM + d];
        sm.yres[m][d] = yv;
        unsigned char msk = (yv == 10000.0f) ? 1 : 0;
        sm.ymask[m][d] = msk;
        cnt += msk ? 0.f : 1.f;
    }

    float sqacc = 0.f;
    const int o = tid & 127;
    const int g = tid >> 7;

    int  slot[4];
    bool sv[4];
    #pragma unroll
    for (int t = 0; t < 4; ++t) { slot[t] = g + 4 * t; sv[t] = slot[t] < tcnt; }

    const unsigned wrowA = s2u(&sm.wstA[o * WST_STRIDE]);
    const unsigned wrowB = s2u(&sm.wstB[o * WST_STRIDE]);
    unsigned xa_a[4], h_a[4];
    #pragma unroll
    for (int t = 0; t < 4; ++t) {
        int s = sv[t] ? slot[t] : 0;
        xa_a[t] = s2u(&sm.xa[s][0]);
        h_a[t]  = s2u(&sm.h[s][0]);
    }

    const float4* wg2 = reinterpret_cast<const float4*>(w2);
    float4 v[8];
    const int jrow = tid >> 5;     // j = tid + r*512 -> row = jrow + r*16, col = jcol
    const int jcol = tid & 31;
    unsigned stB[8];
    #pragma unroll
    for (int r = 0; r < 8; ++r)
        stB[r] = s2u(&sm.wstB[(jrow + r * 16) * WST_STRIDE + jcol]);

    for (int it = 0; it < NITER; ++it) {
        __syncthreads();   // S0: yres/xp/xps stable; all prior wst reads done

        // stage w1 chunk0 -> registers (LDG) and w1 chunk1 -> bufB (cp.async);
        // both complete under phase A
        {
            const float4* wg = reinterpret_cast<const float4*>(
                w1 + (size_t)(it * 256) * IDIM);
            #pragma unroll
            for (int r = 0; r < 8; ++r) v[r] = wg[tid + r * 512];
            const float4* wgc1 = reinterpret_cast<const float4*>(
                w1 + (size_t)(it * 256 + 128) * IDIM);
            #pragma unroll
            for (int r = 0; r < 8; ++r) cpa16(stB[r], wgc1 + tid + r * 512);
            cpa_commit();
        }

        // ================= Phase A: per-warp token pipeline (FFMA2) =========
        if (wid < tcnt) {
            const int m = wid;
            float* xpm  = sm.xp[m];
            float* xpsm = sm.xps[m];
            const float* ym = sm.yres[m];
            const unsigned aA = s2u(xpm);
            const unsigned aB = s2u(xpsm);
            const unsigned aY = s2u(ym);

            float ny2 = 0.f;
            #pragma unroll
            for (int j = 0; j < 4; ++j) { float vv = ym[lane + 32 * j]; ny2 += vv * vv; }
            #pragma unroll
            for (int off = 16; off; off >>= 1) ny2 += __shfl_xor_sync(~0u, ny2, off);
            float ny = sqrtf(ny2);

            ull num2[8], dn2[8];
            #pragma unroll
            for (int k = 0; k < 8; ++k) { num2[k] = 0ull; dn2[k] = 0ull; }
            #pragma unroll
            for (int b = 0; b < 2; ++b) {
                const int q0 = lane + 32 * b;
                const int k0 = 4 * b;
                ull Alo, Ahi, Blo, Bhi;
                lds2(Alo, Ahi, aA + q0 * 16);
                lds2(Blo, Bhi, aB + q0 * 16);
                #pragma unroll 8
                for (int d4 = 0; d4 < 32; ++d4) {
                    ull ylo, yhi, AnL, AnH, BnL, BnH;
                    lds2(ylo, yhi, aY + d4 * 16);
                    lds2(AnL, AnH, aA + (q0 + d4 + 1) * 16);
                    lds2(BnL, BnH, aB + (q0 + d4 + 1) * 16);
                    fma2(num2[k0+0], ylo, Alo); fma2(num2[k0+0], yhi, Ahi);
                    fma2(dn2[k0+0],  Alo, Alo); fma2(dn2[k0+0],  Ahi, Ahi);
                    fma2(num2[k0+1], ylo, Blo); fma2(num2[k0+1], yhi, Bhi);
                    fma2(dn2[k0+1],  Blo, Blo); fma2(dn2[k0+1],  Bhi, Bhi);
                    fma2(num2[k0+2], ylo, Ahi); fma2(num2[k0+2], yhi, AnL);
                    fma2(dn2[k0+2],  Ahi, Ahi); fma2(dn2[k0+2],  AnL, AnL);
                    fma2(num2[k0+3], ylo, Bhi); fma2(num2[k0+3], yhi, BnL);
                    fma2(dn2[k0+3],  Bhi, Bhi); fma2(dn2[k0+3],  BnL, BnL);
                    Alo = AnL; Ahi = AnH; Blo = BnL; Bhi = BnH;
                }
            }

            float best = -INFINITY; int bs = 0x7fffffff;
            #pragma unroll
            for (int b = 0; b < 2; ++b)
            #pragma unroll
            for (int j = 0; j < 4; ++j) {
                int s = 4 * lane + 128 * b + j;
                if (s < 255) {
                    int kk = 4 * b + j;
                    float2 nn = upk(num2[kk]);
                    float2 qq = upk(dn2[kk]);
                    float numv = nn.x + nn.y;
                    float dnv  = qq.x + qq.y;
                    float den = ny * sqrtf(dnv);
                    float sim = (den == 0.f) ? 0.f : numv / den;
                    if (sim > best) { best = sim; bs = s; }
                }
            }
            #pragma unroll
            for (int off = 16; off; off >>= 1) {
                float ob = __shfl_xor_sync(~0u, best, off);
                int   os = __shfl_xor_sync(~0u, bs,   off);
                if (ob > best || (ob == best && os < bs)) { best = ob; bs = os; }
            }
            const int idx = bs;

            float xav[4], z[4];
            float zmax = -INFINITY;
            #pragma unroll
            for (int j = 0; j < 4; ++j) {
                int d = lane + 32 * j;
                xav[j] = xpm[idx + d];
                z[j]   = xav[j] * ym[d];
                zmax   = fmaxf(zmax, z[j]);
            }
            #pragma unroll
            for (int off = 16; off; off >>= 1) zmax = fmaxf(zmax, __shfl_xor_sync(~0u, zmax, off));
            float es = 0.f, e[4];
            #pragma unroll
            for (int j = 0; j < 4; ++j) { e[j] = expf(z[j] - zmax); es += e[j]; }
            #pragma unroll
            for (int off = 16; off; off >>= 1) es += __shfl_xor_sync(~0u, es, off);
            #pragma unroll
            for (int j = 0; j < 4; ++j) {
                int d = lane + 32 * j;
                sm.xa[m][d] = xav[j] * (e[j] / es);
            }
            __syncwarp();
            #pragma unroll
            for (int j = 0; j < 4; ++j) {
                int d = lane + 32 * j;
                int src = d + 127 - idx;
                float xe = (src >= 0 && src < 128) ? sm.xa[m][src] : 0.f;
                xpm[127 + d]  -= xe;
                xpsm[126 + d] -= xe;
            }
        }

        // STS w1c0 -> bufA; cp.async (w1c1 -> bufB) must also be complete
        #pragma unroll
        for (int r = 0; r < 8; ++r)
            sm.wstA[(jrow + r * 16) * WST_STRIDE + jcol] = v[r];
        cpa_wait0();
        __syncthreads();   // S1: xa + bufA + bufB ready

        // prefetch w2 chunk0 -> v (hides under fused B)
        #pragma unroll
        for (int r = 0; r < 8; ++r) {
            int j = tid + r * 512;
            v[r] = wg2[(size_t)(j >> 5) * (HDIM / 4) + it * 64 + (j & 31)];
        }

        // ================= Phase B (fused): channels o and o+128 ============
        {
            float bv0 = b1[it * 256 + o];
            float bv1 = b1[it * 256 + 128 + o];
            ull acc[8];
            acc[0] = pk(bv0, 0.f); acc[1] = pk(bv0, 0.f);
            acc[2] = pk(bv0, 0.f); acc[3] = pk(bv0, 0.f);
            acc[4] = pk(bv1, 0.f); acc[5] = pk(bv1, 0.f);
            acc[6] = pk(bv1, 0.f); acc[7] = pk(bv1, 0.f);
            #pragma unroll 8
            for (int d4 = 0; d4 < 32; ++d4) {
                ull wA01, wA23, wB01, wB23;
                lds2(wA01, wA23, wrowA + d4 * 16);
                lds2(wB01, wB23, wrowB + d4 * 16);
                #pragma unroll
                for (int t = 0; t < 4; ++t) {
                    ull x01, x23;
                    lds2(x01, x23, xa_a[t] + d4 * 16);
                    fma2(acc[t],     wA01, x01); fma2(acc[t],     wA23, x23);
                    fma2(acc[4 + t], wB01, x01); fma2(acc[4 + t], wB23, x23);
                }
            }
            #pragma unroll
            for (int t = 0; t < 4; ++t) {
                if (sv[t]) {
                    float2 a0 = upk(acc[t]);
                    float2 a1 = upk(acc[4 + t]);
                    sm.h[slot[t]][o]       = a0.x + a0.y;
                    sm.h[slot[t]][128 + o] = a1.x + a1.y;
                }
            }
        }
        __syncthreads();   // SBe: B compute done; bufA/bufB free; h written

        // ================= Phase C: y_ele = h @ W2_slice^T + b2 =============
        float b2v = b2[o];
        ull accc[4];
        accc[0] = pk(b2v, 0.f); accc[1] = pk(b2v, 0.f);
        accc[2] = pk(b2v, 0.f); accc[3] = pk(b2v, 0.f);

        // STS w2c0 -> bufA; LDG w2c1 -> v (hides under C chunk0)
        #pragma unroll
        for (int r = 0; r < 8; ++r)
            sm.wstA[(jrow + r * 16) * WST_STRIDE + jcol] = v[r];
        __syncthreads();   // S3: bufA ready
        #pragma unroll
        for (int r = 0; r < 8; ++r) {
            int j = tid + r * 512;
            v[r] = wg2[(size_t)(j >> 5) * (HDIM / 4) + it * 64 + 32 + (j & 31)];
        }

        // ---- C chunk0 from bufA ----
        #pragma unroll 8
        for (int c4 = 0; c4 < 32; ++c4) {
            ull w01, w23;
            lds2(w01, w23, wrowA + c4 * 16);
            #pragma unroll
            for (int t = 0; t < 4; ++t) {
                ull h01, h23;
                lds2(h01, h23, h_a[t] + c4 * 16);
                fma2(accc[t], w01, h01);
                fma2(accc[t], w23, h23);
            }
        }
        // STS w2c1 -> bufB
        #pragma unroll
        for (int r = 0; r < 8; ++r)
            sm.wstB[(jrow + r * 16) * WST_STRIDE + jcol] = v[r];
        __syncthreads();   // S4: bufB ready

        // ---- C chunk1 from bufB ----
        #pragma unroll 8
        for (int c4 = 0; c4 < 32; ++c4) {
            ull w01, w23;
            lds2(w01, w23, wrowB + c4 * 16);
            #pragma unroll
            for (int t = 0; t < 4; ++t) {
                ull h01, h23;
                lds2(h01, h23, h_a[t] + 512 + c4 * 16);
                fma2(accc[t], w01, h01);
                fma2(accc[t], w23, h23);
            }
        }

        // ---- masked squared error + y_res update ----
        #pragma unroll
        for (int t = 0; t < 4; ++t) {
            if (sv[t]) {
                int m = slot[t];
                float2 c2 = upk(accc[t]);
                float ye = c2.x + c2.y;
                float yr = sm.yres[m][o];
                if (!sm.ymask[m][o]) { float dd = ye - yr; sqacc += dd * dd; }
                sm.yres[m][o] = yr - ye;
            }
        }
        // loop-top S0 orders these writes before next phase A / restage
    }

    // ---- block reduction ----
    #pragma unroll
    for (int off = 16; off; off >>= 1) {
        sqacc += __shfl_xor_sync(~0u, sqacc, off);
        cnt   += __shfl_xor_sync(~0u, cnt,   off);
    }
    if (lane == 0) { sm.red[wid] = sqacc; sm.red2[wid] = cnt; }
    __syncthreads();
    if (tid == 0) {
        float s = 0.f, c = 0.f;
        #pragma unroll
        for (int w = 0; w < 16; ++w) { s += sm.red[w]; c += sm.red2[w]; }
        g_psum[blk] = s;
        g_pcnt[blk] = c;
        __threadfence();
        int ticket = atomicAdd(&g_cnt, 1);
        __threadfence();
        sm.islast = (ticket == NBLK - 1) ? 1 : 0;
    }
    __syncthreads();

    // ---- last block: deterministic global reduction ----
    if (sm.islast) {
        int t = tid;
        if (t < 256) {
            sm.fred[t]  = (t < NBLK) ? g_psum[t] : 0.f;
            sm.fred2[t] = (t < NBLK) ? g_pcnt[t] : 0.f;
        }
        __syncthreads();
        for (int off = 128; off; off >>= 1) {
            if (t < off) { sm.fred[t] += sm.fred[t + off]; sm.fred2[t] += sm.fred2[t + off]; }
            __syncthreads();
        }
        if (t == 0) {
            out[0] = sm.fred[0] / (4.0f * sm.fred2[0]);
            g_cnt = 0;   // reset for next graph replay
        }
    }
}

extern "C" void kernel_launch(void* const* d_in, const int* in_sizes, int n_in,
                              void* d_out, int out_size)
{
    (void)in_sizes; (void)n_in; (void)out_size;
    const float* x  = (const float*)d_in[0];
    const float* y  = (const float*)d_in[1];
    const float* w1 = (const float*)d_in[2];
    const float* b1 = (const float*)d_in[3];
    const float* w2 = (const float*)d_in[4];
    const float* b2 = (const float*)d_in[5];
    float* out = (float*)d_out;

    cudaFuncSetAttribute(net_main_kernel,
                         cudaFuncAttributeMaxDynamicSharedMemorySize,
                         (int)sizeof(Smem));
    net_main_kernel<<<NBLK, NTHREADS, sizeof(Smem)>>>(x, y, w1, b1, w2, b2, out);
}

// round 14
// speedup vs baseline: 2.0431x; 1.0777x over previous
#include <cuda_runtime.h>
#include <math.h>

#define IDIM 128
#define HDIM 1024
#define NITER 4
#define NTOK 2048
#define NBLK 148            // one block per SM, balanced wave
#define NTHREADS 512        // 16 warps
#define TOKMAX 14           // blocks 0..123: 14 tokens, 124..147: 13
#define XPAD 384            // padded x_res (data at [127,254], zeros elsewhere)
#define WST_STRIDE 33       // float4 stride per staged weight row (conflict-free)
#define HROW 264            // h row stride in floats
#define PROW 388            // prefix-sum row stride (float4-aligned)

typedef unsigned long long ull;

__device__ float g_psum[NBLK];
__device__ float g_pcnt[NBLK];
__device__ int   g_cnt = 0;          // last-block ticket; reset by last block

// ---- packed fp32x2 helpers ----
__device__ __forceinline__ ull pk(float lo, float hi) {
    ull r; asm("mov.b64 %0, {%1, %2};" : "=l"(r) : "f"(lo), "f"(hi)); return r;
}
__device__ __forceinline__ void fma2(ull& acc, ull a, ull b) {
    asm("fma.rn.f32x2 %0, %1, %2, %3;" : "=l"(acc) : "l"(a), "l"(b), "l"(acc));
}
__device__ __forceinline__ float2 upk(ull v) {
    float2 r; asm("mov.b64 {%0, %1}, %2;" : "=f"(r.x), "=f"(r.y) : "l"(v)); return r;
}
__device__ __forceinline__ void lds2(ull& a, ull& b, unsigned addr) {
    asm("ld.shared.v2.b64 {%0, %1}, [%2];" : "=l"(a), "=l"(b) : "r"(addr));
}
__device__ __forceinline__ unsigned s2u(const void* p) {
    unsigned a;
    asm("{ .reg .u64 t; cvta.to.shared.u64 t, %1; cvt.u32.u64 %0, t; }"
        : "=r"(a) : "l"(p));
    return a;
}
__device__ __forceinline__ void cpa16(unsigned saddr, const void* g) {
    asm volatile("cp.async.cg.shared.global [%0], [%1], 16;"
                 :: "r"(saddr), "l"(g) : "memory");
}
__device__ __forceinline__ void cpa_commit() {
    asm volatile("cp.async.commit_group;" ::: "memory");
}
__device__ __forceinline__ void cpa_wait0() {
    asm volatile("cp.async.wait_group 0;" ::: "memory");
}

struct __align__(16) Smem {
    float4 wstA[IDIM * WST_STRIDE];    // 67584 B  staged weights, buffer A
    float4 wstB[IDIM * WST_STRIDE];    // 67584 B  staged weights, buffer B
    float  xp[TOKMAX][XPAD];           // 21504 B  padded x_res
    float  P[TOKMAX][PROW];            // 21728 B  prefix sums of squares
    float  xa[TOKMAX][IDIM];           // 7168 B
    float  h[TOKMAX][HROW];            // 14784 B
    float  yres[TOKMAX][IDIM];         // 7168 B
    float  red[16];
    float  red2[16];
    float  fred[256];
    float  fred2[256];
    int    islast;
    unsigned char ymask[TOKMAX][IDIM]; // 1792 B
};

extern __shared__ unsigned char smem_raw[];

__global__ void __launch_bounds__(NTHREADS, 1)
net_main_kernel(const float* __restrict__ x, const float* __restrict__ y,
                const float* __restrict__ w1, const float* __restrict__ b1,
                const float* __restrict__ w2, const float* __restrict__ b2,
                float* __restrict__ out)
{
    Smem& sm = *reinterpret_cast<Smem*>(smem_raw);
    const int tid  = threadIdx.x;
    const int lane = tid & 31;
    const int wid  = tid >> 5;
    const int blk  = blockIdx.x;
    const int tcnt = (blk < 124) ? 14 : 13;
    const int tok0 = (blk < 124) ? blk * 14 : 124 * 14 + (blk - 124) * 13;

    // ---- zero padded x buffer ----
    for (int e = tid; e < TOKMAX * XPAD; e += NTHREADS)
        (&sm.xp[0][0])[e] = 0.f;
    __syncthreads();

    // ---- load x, y, mask; count unmasked ----
    float cnt = 0.f;
    for (int e = tid; e < tcnt * IDIM; e += NTHREADS) {
        int m = e >> 7, d = e & 127;
        sm.xp[m][127 + d] = x[(tok0 + m) * IDIM + d];
        float yv = y[(tok0 + m) * IDIM + d];
        sm.yres[m][d] = yv;
        unsigned char msk = (yv == 10000.0f) ? 1 : 0;
        sm.ymask[m][d] = msk;
        cnt += msk ? 0.f : 1.f;
    }

    float sqacc = 0.f;
    const int o = tid & 127;
    const int g = tid >> 7;

    int  slot[4];
    bool sv[4];
    #pragma unroll
    for (int t = 0; t < 4; ++t) { slot[t] = g + 4 * t; sv[t] = slot[t] < tcnt; }

    const unsigned wrowA = s2u(&sm.wstA[o * WST_STRIDE]);
    const unsigned wrowB = s2u(&sm.wstB[o * WST_STRIDE]);
    unsigned xa_a[4], h_a[4];
    #pragma unroll
    for (int t = 0; t < 4; ++t) {
        int s = sv[t] ? slot[t] : 0;
        xa_a[t] = s2u(&sm.xa[s][0]);
        h_a[t]  = s2u(&sm.h[s][0]);
    }

    const float4* wg2 = reinterpret_cast<const float4*>(w2);
    float4 v[8];
    const int jrow = tid >> 5;     // j = tid + r*512 -> row = jrow + r*16, col = jcol
    const int jcol = tid & 31;
    unsigned stB[8];
    #pragma unroll
    for (int r = 0; r < 8; ++r)
        stB[r] = s2u(&sm.wstB[(jrow + r * 16) * WST_STRIDE + jcol]);

    for (int it = 0; it < NITER; ++it) {
        __syncthreads();   // S0: yres/xp stable; all prior wst reads done

        // stage w1 chunk0 -> registers (LDG) and w1 chunk1 -> bufB (cp.async);
        // both complete under phase A
        {
            const float4* wg = reinterpret_cast<const float4*>(
                w1 + (size_t)(it * 256) * IDIM);
            #pragma unroll
            for (int r = 0; r < 8; ++r) v[r] = wg[tid + r * 512];
            const float4* wgc1 = reinterpret_cast<const float4*>(
                w1 + (size_t)(it * 256 + 128) * IDIM);
            #pragma unroll
            for (int r = 0; r < 8; ++r) cpa16(stB[r], wgc1 + tid + r * 512);
            cpa_commit();
        }

        // ================= Phase A: per-warp token pipeline ================
        if (wid < tcnt) {
            const int m = wid;
            float* xpm = sm.xp[m];
            const float* ym = sm.yres[m];
            const unsigned aA = s2u(xpm);
            const unsigned aY = s2u(ym);
            float* Pm = sm.P[m];
            const float4* xp4 = reinterpret_cast<const float4*>(xpm);

            // ---- prefix sums of squares: P[i] = sum_{k<i} xp[k]^2 ----
            {
                const float4* b3 = xp4 + lane * 3;
                float4 a = b3[0], b = b3[1], c = b3[2];
                float s[12];
                s[0]  = a.x * a.x;
                s[1]  = fmaf(a.y, a.y, s[0]);
                s[2]  = fmaf(a.z, a.z, s[1]);
                s[3]  = fmaf(a.w, a.w, s[2]);
                s[4]  = fmaf(b.x, b.x, s[3]);
                s[5]  = fmaf(b.y, b.y, s[4]);
                s[6]  = fmaf(b.z, b.z, s[5]);
                s[7]  = fmaf(b.w, b.w, s[6]);
                s[8]  = fmaf(c.x, c.x, s[7]);
                s[9]  = fmaf(c.y, c.y, s[8]);
                s[10] = fmaf(c.z, c.z, s[9]);
                s[11] = fmaf(c.w, c.w, s[10]);
                float incl = s[11];
                #pragma unroll
                for (int off = 1; off < 32; off <<= 1) {
                    float t = __shfl_up_sync(~0u, incl, off);
                    if (lane >= off) incl += t;
                }
                float excl = incl - s[11];
                if (lane == 0) Pm[0] = 0.f;
                #pragma unroll
                for (int j = 0; j < 12; ++j)
                    Pm[lane * 12 + j + 1] = excl + s[j];
            }

            // ||y_res||
            float ny2 = 0.f;
            #pragma unroll
            for (int j = 0; j < 4; ++j) { float vv = ym[lane + 32 * j]; ny2 += vv * vv; }
            #pragma unroll
            for (int off = 16; off; off >>= 1) ny2 += __shfl_xor_sync(~0u, ny2, off);
            float ny = sqrtf(ny2);
            __syncwarp();   // P visible to all lanes

            // banded correlation (num only): shifts s = 4*lane + 128*b + j
            // even j via aligned FFMA2; odd j via scalar FFMA from register window
            ull   nume[4];     // [2b + (j==2)]
            float numo[4];     // [2b + (j==3)]
            #pragma unroll
            for (int k = 0; k < 4; ++k) { nume[k] = 0ull; numo[k] = 0.f; }
            #pragma unroll
            for (int b = 0; b < 2; ++b) {
                const int q0 = lane + 32 * b;
                const int k0 = 2 * b;
                ull Alo, Ahi;
                lds2(Alo, Ahi, aA + q0 * 16);
                #pragma unroll 8
                for (int d4 = 0; d4 < 32; ++d4) {
                    ull ylo, yhi, AnL, AnH;
                    lds2(ylo, yhi, aY + d4 * 16);
                    lds2(AnL, AnH, aA + (q0 + d4 + 1) * 16);
                    // j=0: (x0,x1),(x2,x3)
                    fma2(nume[k0],     ylo, Alo); fma2(nume[k0],     yhi, Ahi);
                    // j=2: (x2,x3),(x4,x5)
                    fma2(nume[k0 + 1], ylo, Ahi); fma2(nume[k0 + 1], yhi, AnL);
                    // scalar components (free register aliasing)
                    float2 y01 = upk(ylo), y23 = upk(yhi);
                    float2 x01 = upk(Alo), x23 = upk(Ahi);
                    float2 x45 = upk(AnL), x67 = upk(AnH);
                    // j=1: y0*x1 + y1*x2 + y2*x3 + y3*x4
                    float n1 = numo[k0];
                    n1 = fmaf(y01.x, x01.y, n1);
                    n1 = fmaf(y01.y, x23.x, n1);
                    n1 = fmaf(y23.x, x23.y, n1);
                    n1 = fmaf(y23.y, x45.x, n1);
                    numo[k0] = n1;
                    // j=3: y0*x3 + y1*x4 + y2*x5 + y3*x6
                    float n3 = numo[k0 + 1];
                    n3 = fmaf(y01.x, x23.y, n3);
                    n3 = fmaf(y01.y, x45.x, n3);
                    n3 = fmaf(y23.x, x45.y, n3);
                    n3 = fmaf(y23.y, x67.x, n3);
                    numo[k0 + 1] = n3;
                    Alo = AnL; Ahi = AnH;
                }
            }

            // first-max using prefix-difference window norms
            const float4* P4m = reinterpret_cast<const float4*>(Pm);
            float best = -INFINITY; int bs = 0x7fffffff;
            #pragma unroll
            for (int b = 0; b < 2; ++b) {
                float4 Plo = P4m[lane + 32 * b];
                float4 Phi = P4m[lane + 32 * b + 32];
                float dnv[4] = {fmaxf(Plo.x >= Phi.x ? 0.f : Phi.x - Plo.x, Phi.x - Plo.x),
                                0.f, 0.f, 0.f};
                dnv[0] = fmaxf(Phi.x - Plo.x, 0.f);
                dnv[1] = fmaxf(Phi.y - Plo.y, 0.f);
                dnv[2] = fmaxf(Phi.z - Plo.z, 0.f);
                dnv[3] = fmaxf(Phi.w - Plo.w, 0.f);
                const int k0 = 2 * b;
                float2 ne0 = upk(nume[k0]);
                float2 ne2 = upk(nume[k0 + 1]);
                float nums[4] = {ne0.x + ne0.y, numo[k0], ne2.x + ne2.y, numo[k0 + 1]};
                #pragma unroll
                for (int j = 0; j < 4; ++j) {
                    int s = 4 * lane + 128 * b + j;
                    if (s < 255) {
                        float den = ny * sqrtf(dnv[j]);
                        float sim = (den == 0.f) ? 0.f : nums[j] / den;
                        if (sim > best) { best = sim; bs = s; }
                    }
                }
            }
            #pragma unroll
            for (int off = 16; off; off >>= 1) {
                float ob = __shfl_xor_sync(~0u, best, off);
                int   os = __shfl_xor_sync(~0u, bs,   off);
                if (ob > best || (ob == best && os < bs)) { best = ob; bs = os; }
            }
            const int idx = bs;

            float xav[4], z[4];
            float zmax = -INFINITY;
            #pragma unroll
            for (int j = 0; j < 4; ++j) {
                int d = lane + 32 * j;
                xav[j] = xpm[idx + d];
                z[j]   = xav[j] * ym[d];
                zmax   = fmaxf(zmax, z[j]);
            }
            #pragma unroll
            for (int off = 16; off; off >>= 1) zmax = fmaxf(zmax, __shfl_xor_sync(~0u, zmax, off));
            float es = 0.f, e[4];
            #pragma unroll
            for (int j = 0; j < 4; ++j) { e[j] = expf(z[j] - zmax); es += e[j]; }
            #pragma unroll
            for (int off = 16; off; off >>= 1) es += __shfl_xor_sync(~0u, es, off);
            #pragma unroll
            for (int j = 0; j < 4; ++j) {
                int d = lane + 32 * j;
                sm.xa[m][d] = xav[j] * (e[j] / es);
            }
            __syncwarp();
            #pragma unroll
            for (int j = 0; j < 4; ++j) {
                int d = lane + 32 * j;
                int src = d + 127 - idx;
                float xe = (src >= 0 && src < 128) ? sm.xa[m][src] : 0.f;
                xpm[127 + d] -= xe;
            }
        }

        // STS w1c0 -> bufA; cp.async (w1c1 -> bufB) must also be complete
        #pragma unroll
        for (int r = 0; r < 8; ++r)
            sm.wstA[(jrow + r * 16) * WST_STRIDE + jcol] = v[r];
        cpa_wait0();
        __syncthreads();   // S1: xa + bufA + bufB ready

        // prefetch w2 chunk0 -> v (hides under fused B)
        #pragma unroll
        for (int r = 0; r < 8; ++r) {
            int j = tid + r * 512;
            v[r] = wg2[(size_t)(j >> 5) * (HDIM / 4) + it * 64 + (j & 31)];
        }

        // ================= Phase B (fused): channels o and o+128 ============
        {
            float bv0 = b1[it * 256 + o];
            float bv1 = b1[it * 256 + 128 + o];
            ull acc[8];
            acc[0] = pk(bv0, 0.f); acc[1] = pk(bv0, 0.f);
            acc[2] = pk(bv0, 0.f); acc[3] = pk(bv0, 0.f);
            acc[4] = pk(bv1, 0.f); acc[5] = pk(bv1, 0.f);
            acc[6] = pk(bv1, 0.f); acc[7] = pk(bv1, 0.f);
            #pragma unroll 8
            for (int d4 = 0; d4 < 32; ++d4) {
                ull wA01, wA23, wB01, wB23;
                lds2(wA01, wA23, wrowA + d4 * 16);
                lds2(wB01, wB23, wrowB + d4 * 16);
                #pragma unroll
                for (int t = 0; t < 4; ++t) {
                    ull x01, x23;
                    lds2(x01, x23, xa_a[t] + d4 * 16);
                    fma2(acc[t],     wA01, x01); fma2(acc[t],     wA23, x23);
                    fma2(acc[4 + t], wB01, x01); fma2(acc[4 + t], wB23, x23);
                }
            }
            #pragma unroll
            for (int t = 0; t < 4; ++t) {
                if (sv[t]) {
                    float2 a0 = upk(acc[t]);
                    float2 a1 = upk(acc[4 + t]);
                    sm.h[slot[t]][o]       = a0.x + a0.y;
                    sm.h[slot[t]][128 + o] = a1.x + a1.y;
                }
            }
        }
        __syncthreads();   // SBe: B compute done; bufA/bufB free; h written

        // ================= Phase C: y_ele = h @ W2_slice^T + b2 =============
        float b2v = b2[o];
        ull accc[4];
        accc[0] = pk(b2v, 0.f); accc[1] = pk(b2v, 0.f);
        accc[2] = pk(b2v, 0.f); accc[3] = pk(b2v, 0.f);

        // STS w2c0 -> bufA; LDG w2c1 -> v (hides under C chunk0)
        #pragma unroll
        for (int r = 0; r < 8; ++r)
            sm.wstA[(jrow + r * 16) * WST_STRIDE + jcol] = v[r];
        __syncthreads();   // S3: bufA ready
        #pragma unroll
        for (int r = 0; r < 8; ++r) {
            int j = tid + r * 512;
            v[r] = wg2[(size_t)(j >> 5) * (HDIM / 4) + it * 64 + 32 + (j & 31)];
        }

        // ---- C chunk0 from bufA ----
        #pragma unroll 8
        for (int c4 = 0; c4 < 32; ++c4) {
            ull w01, w23;
            lds2(w01, w23, wrowA + c4 * 16);
            #pragma unroll
            for (int t = 0; t < 4; ++t) {
                ull h01, h23;
                lds2(h01, h23, h_a[t] + c4 * 16);
                fma2(accc[t], w01, h01);
                fma2(accc[t], w23, h23);
            }
        }
        // STS w2c1 -> bufB
        #pragma unroll
        for (int r = 0; r < 8; ++r)
            sm.wstB[(jrow + r * 16) * WST_STRIDE + jcol] = v[r];
        __syncthreads();   // S4: bufB ready

        // ---- C chunk1 from bufB ----
        #pragma unroll 8
        for (int c4 = 0; c4 < 32; ++c4) {
            ull w01, w23;
            lds2(w01, w23, wrowB + c4 * 16);
            #pragma unroll
            for (int t = 0; t < 4; ++t) {
                ull h01, h23;
                lds2(h01, h23, h_a[t] + 512 + c4 * 16);
                fma2(accc[t], w01, h01);
                fma2(accc[t], w23, h23);
            }
        }

        // ---- masked squared error + y_res update ----
        #pragma unroll
        for (int t = 0; t < 4; ++t) {
            if (sv[t]) {
                int m = slot[t];
                float2 c2 = upk(accc[t]);
                float ye = c2.x + c2.y;
                float yr = sm.yres[m][o];
                if (!sm.ymask[m][o]) { float dd = ye - yr; sqacc += dd * dd; }
                sm.yres[m][o] = yr - ye;
            }
        }
        // loop-top S0 orders these writes before next phase A / restage
    }

    // ---- block reduction ----
    #pragma unroll
    for (int off = 16; off; off >>= 1) {
        sqacc += __shfl_xor_sync(~0u, sqacc, off);
        cnt   += __shfl_xor_sync(~0u, cnt,   off);
    }
    if (lane == 0) { sm.red[wid] = sqacc; sm.red2[wid] = cnt; }
    __syncthreads();
    if (tid == 0) {
        float s = 0.f, c = 0.f;
        #pragma unroll
        for (int w = 0; w < 16; ++w) { s += sm.red[w]; c += sm.red2[w]; }
        g_psum[blk] = s;
        g_pcnt[blk] = c;
        __threadfence();
        int ticket = atomicAdd(&g_cnt, 1);
        __threadfence();
        sm.islast = (ticket == NBLK - 1) ? 1 : 0;
    }
    __syncthreads();

    // ---- last block: deterministic global reduction ----
    if (sm.islast) {
        int t = tid;
        if (t < 256) {
            sm.fred[t]  = (t < NBLK) ? g_psum[t] : 0.f;
            sm.fred2[t] = (t < NBLK) ? g_pcnt[t] : 0.f;
        }
        __syncthreads();
        for (int off = 128; off; off >>= 1) {
            if (t < off) { sm.fred[t] += sm.fred[t + off]; sm.fred2[t] += sm.fred2[t + off]; }
            __syncthreads();
        }
        if (t == 0) {
            out[0] = sm.fred[0] / (4.0f * sm.fred2[0]);
            g_cnt = 0;   // reset for next graph replay
        }
    }
}

extern "C" void kernel_launch(void* const* d_in, const int* in_sizes, int n_in,
                              void* d_out, int out_size)
{
    (void)in_sizes; (void)n_in; (void)out_size;
    const float* x  = (const float*)d_in[0];
    const float* y  = (const float*)d_in[1];
    const float* w1 = (const float*)d_in[2];
    const float* b1 = (const float*)d_in[3];
    const float* w2 = (const float*)d_in[4];
    const float* b2 = (const float*)d_in[5];
    float* out = (float*)d_out;

    cudaFuncSetAttribute(net_main_kernel,
                         cudaFuncAttributeMaxDynamicSharedMemorySize,
                         (int)sizeof(Smem));
    net_main_kernel<<<NBLK, NTHREADS, sizeof(Smem)>>>(x, y, w1, b1, w2, b2, out);
}